// round 1
// baseline (speedup 1.0000x reference)
#include <cuda_runtime.h>
#include <cstdint>

#define BB 32
#define LL 128
#define FF 128
#define RR 4096
#define HH (RR >> 1)

// Vector float4 global reduction (no return) — sm_90+.
__device__ __forceinline__ void red4(float* p, float c, float4 v) {
    asm volatile("red.global.add.v4.f32 [%0], {%1, %2, %3, %4};"
                 :: "l"(p), "f"(c * v.x), "f"(c * v.y), "f"(c * v.z), "f"(c * v.w)
                 : "memory");
}

// Pass 1: out[b,r,f] = (r==1) ? d2[b]*root_filler[b,f] : 0
// One float4 per thread. B*R*F/4 = 4,194,304 float4s.
__global__ void dti_init_kernel(float4* __restrict__ out,
                                const float4* __restrict__ root_filler,
                                const float* __restrict__ op_dist) {
    int idx = blockIdx.x * blockDim.x + threadIdx.x;       // float4 index
    int row = idx >> 5;                                    // F/4 = 32 float4 per row
    int r = row & (RR - 1);
    float4 v = make_float4(0.f, 0.f, 0.f, 0.f);
    if (r == 1) {
        int b = row >> 12;                                 // row / R
        float d2 = __ldg(op_dist + b * 3 + 2);
        float4 rf = __ldg(root_filler + b * (FF / 4) + (idx & 31));
        v = make_float4(d2 * rf.x, d2 * rf.y, d2 * rf.z, d2 * rf.w);
    }
    out[idx] = v;
}

// Pass 2: one warp per input element. Lane l handles features [4l, 4l+4).
// Each element contributes to <=4 output rows via vector reductions.
__global__ void dti_scatter_kernel(const float4* __restrict__ mem,
                                   const float4* __restrict__ arg_w,   // (B*L) float4
                                   const float* __restrict__ op_dist,  // (B,3)
                                   const int* __restrict__ batch_idx,
                                   const int* __restrict__ slot_idx,
                                   const int* __restrict__ role_idx,
                                   float* __restrict__ out,
                                   int n) {
    int e = (blockIdx.x * blockDim.x + threadIdx.x) >> 5;
    if (e >= n) return;
    int lane = threadIdx.x & 31;

    // Coalesced 512B load of the element's feature row.
    float4 v = __ldg(mem + (size_t)e * (FF / 4) + lane);

    // Skip fully-zero rows (contribute nothing anywhere).
    bool z = (v.x == 0.f) & (v.y == 0.f) & (v.z == 0.f) & (v.w == 0.f);
    if (__ballot_sync(0xffffffffu, z) == 0xffffffffu) return;

    int b = __ldg(batch_idx + e);
    int s = __ldg(slot_idx + e);
    int j = __ldg(role_idx + e);

    float4 w = __ldg(arg_w + b * LL + s);
    float d0 = __ldg(op_dist + b * 3 + 0);
    float d1 = __ldg(op_dist + b * 3 + 1);
    float d2 = __ldg(op_dist + b * 3 + 2);

    size_t base = (size_t)b * RR * FF + (size_t)lane * 4;

    if ((j & 1) == 0) {
        // car: out row j/2, coeff d0*w0  (j/2 < H always)
        red4(out + base + (size_t)(j >> 1) * FF, d0 * w.x, v);
    } else if (j >= 3) {
        // cdr: out row (j-1)/2, coeff d1*w1 (row 0 excluded by j>=3)
        red4(out + base + (size_t)((j - 1) >> 1) * FF, d1 * w.y, v);
    }
    if (j < HH) {
        // cons: rows 2j (coeff d2*w2) and 2j+1 (coeff d2*w3)
        float* p = out + base + (size_t)(2 * j) * FF;
        red4(p, d2 * w.z, v);
        red4(p + FF, d2 * w.w, v);
    }
}

extern "C" void kernel_launch(void* const* d_in, const int* in_sizes, int n_in,
                              void* d_out, int out_size) {
    const float* mem = (const float*)d_in[0];
    const float* aw  = (const float*)d_in[1];
    const float* rf  = (const float*)d_in[2];
    const float* od  = (const float*)d_in[3];
    const int* bi    = (const int*)d_in[4];
    const int* si    = (const int*)d_in[5];
    const int* ri    = (const int*)d_in[6];
    float* out       = (float*)d_out;

    int n = in_sizes[4];  // N elements

    // Pass 1: init output (zeros + scaled root_filler at row 1).
    int n_f4 = BB * RR * FF / 4;
    dti_init_kernel<<<n_f4 / 256, 256>>>((float4*)out, (const float4*)rf, od);

    // Pass 2: fused scatter with vector reductions. One warp per element.
    int threads = 256;
    int warps_per_block = threads / 32;
    int blocks = (n + warps_per_block - 1) / warps_per_block;
    dti_scatter_kernel<<<blocks, threads>>>((const float4*)mem, (const float4*)aw, od,
                                            bi, si, ri, out, n);
}

// round 2
// speedup vs baseline: 1.0005x; 1.0005x over previous
#include <cuda_runtime.h>
#include <cstdint>

#define BB 32
#define LL 128
#define FF 128
#define RR 4096
#define HH (RR >> 1)

// Vector float4 global reduction (no return) — sm_90+.
__device__ __forceinline__ void red4(float* p, float c, float4 v) {
    asm volatile("red.global.add.v4.f32 [%0], {%1, %2, %3, %4};"
                 :: "l"(p), "f"(c * v.x), "f"(c * v.y), "f"(c * v.z), "f"(c * v.w)
                 : "memory");
}

// Streaming (evict-first) 128-bit load: don't let this 134MB stream evict the
// 67MB output working set from L2.
__device__ __forceinline__ float4 ldcs4(const float4* p) {
    float4 v;
    asm volatile("ld.global.cs.v4.f32 {%0, %1, %2, %3}, [%4];"
                 : "=f"(v.x), "=f"(v.y), "=f"(v.z), "=f"(v.w) : "l"(p));
    return v;
}

// Tiny kernel: out[b, 1, :] = d2[b] * root_filler[b, :]  (runs after memset).
__global__ void dti_rf_kernel(float4* __restrict__ out,
                              const float4* __restrict__ root_filler,
                              const float* __restrict__ op_dist) {
    int idx = blockIdx.x * blockDim.x + threadIdx.x;   // 0 .. B*32-1
    int b = idx >> 5;
    int f4 = idx & 31;
    float d2 = __ldg(op_dist + b * 3 + 2);
    float4 rf = __ldg(root_filler + b * (FF / 4) + f4);
    out[(size_t)b * RR * (FF / 4) + 1 * (FF / 4) + f4] =
        make_float4(d2 * rf.x, d2 * rf.y, d2 * rf.z, d2 * rf.w);
}

// One warp per input element. Lane l handles features [4l, 4l+4).
// Each element contributes to <=3 output rows via vector reductions.
__global__ void dti_scatter_kernel(const float4* __restrict__ mem,
                                   const float4* __restrict__ arg_w,   // (B*L) float4
                                   const float* __restrict__ op_dist,  // (B,3)
                                   const int* __restrict__ batch_idx,
                                   const int* __restrict__ slot_idx,
                                   const int* __restrict__ role_idx,
                                   float* __restrict__ out,
                                   int n) {
    int e = (blockIdx.x * blockDim.x + threadIdx.x) >> 5;
    if (e >= n) return;
    int lane = threadIdx.x & 31;

    // Coalesced 512B streaming load of the element's feature row.
    float4 v = ldcs4(mem + (size_t)e * (FF / 4) + lane);

    // Skip fully-zero rows (contribute nothing anywhere).
    bool z = (v.x == 0.f) & (v.y == 0.f) & (v.z == 0.f) & (v.w == 0.f);
    if (__ballot_sync(0xffffffffu, z) == 0xffffffffu) return;

    int b = __ldg(batch_idx + e);
    int s = __ldg(slot_idx + e);
    int j = __ldg(role_idx + e);

    float4 w = __ldg(arg_w + b * LL + s);
    float d0 = __ldg(op_dist + b * 3 + 0);
    float d1 = __ldg(op_dist + b * 3 + 1);
    float d2 = __ldg(op_dist + b * 3 + 2);

    size_t base = (size_t)b * RR * FF + (size_t)lane * 4;

    if ((j & 1) == 0) {
        // car: out row j/2, coeff d0*w0  (j/2 < H always)
        red4(out + base + (size_t)(j >> 1) * FF, d0 * w.x, v);
    } else if (j >= 3) {
        // cdr: out row (j-1)/2, coeff d1*w1 (row 0 excluded by j>=3)
        red4(out + base + (size_t)((j - 1) >> 1) * FF, d1 * w.y, v);
    }
    if (j < HH) {
        // cons: rows 2j (coeff d2*w2) and 2j+1 (coeff d2*w3)
        float* p = out + base + (size_t)(2 * j) * FF;
        red4(p, d2 * w.z, v);
        red4(p + FF, d2 * w.w, v);
    }
}

extern "C" void kernel_launch(void* const* d_in, const int* in_sizes, int n_in,
                              void* d_out, int out_size) {
    const float* mem = (const float*)d_in[0];
    const float* aw  = (const float*)d_in[1];
    const float* rf  = (const float*)d_in[2];
    const float* od  = (const float*)d_in[3];
    const int* bi    = (const int*)d_in[4];
    const int* si    = (const int*)d_in[5];
    const int* ri    = (const int*)d_in[6];
    float* out       = (float*)d_out;

    int n = in_sizes[4];  // N elements

    // Pass 1: zero output (memset node, near-peak write BW; leaves lines dirty
    // in L2), then write d2*root_filler into row 1 of each batch.
    cudaMemsetAsync(d_out, 0, (size_t)out_size * sizeof(float), 0);
    dti_rf_kernel<<<BB * (FF / 4) / 256, 256>>>((float4*)out, (const float4*)rf, od);

    // Pass 2: fused scatter with vector reductions. One warp per element.
    int threads = 256;
    int warps_per_block = threads / 32;
    int blocks = (n + warps_per_block - 1) / warps_per_block;
    dti_scatter_kernel<<<blocks, threads>>>((const float4*)mem, (const float4*)aw, od,
                                            bi, si, ri, out, n);
}